// round 15
// baseline (speedup 1.0000x reference)
#include <cuda_runtime.h>
#include <cuda_fp16.h>
#include <math.h>

#define NN 100000
#define EE 1600000
#define INC 32
#define HC  64
#define LC  16
#define GG  64
#define NB1 98          // ceil(NN/1024) scan blocks

// ---- device scratch (static, no allocation) ----
__device__ int   g_degi[NN];
__device__ int   g_part[NN];
__device__ int   g_off[NN];
__device__ int   g_cur[NN];
__device__ int   g_csr[EE];
__device__ uint2 g_edat[EE];        // {dinv[src] bits, batch[src]} per CSR slot
__device__ int   g_bsum[128];
__device__ float g_dinv[NN];
__device__ __half g_xd[NN * INC];   // x * dinv, fp16 rows
__device__ float g_xws[NN * HC];    // payload: fp32 rows OR packed half rows
__device__ float g_buf0[NN * HC];
__device__ float g_buf1[NN * HC];
__device__ float g_sums[GG * HC];
__device__ float g_cnt[GG];
__device__ float g_XW[GG * HC];     // (relu(z@Wdp+b)) @ W_dec0, per graph

// ------------------------------------------------------------------
__global__ void k_init() {
    int i = blockIdx.x * blockDim.x + threadIdx.x;
    if (i < NN) g_degi[i] = 0;
    if (i < GG * HC) g_sums[i] = 0.f;
    if (i < GG) g_cnt[i] = 0.f;
}

__global__ void k_count(const int* __restrict__ ei) {
    int e = blockIdx.x * blockDim.x + threadIdx.x;
    if (e < EE) atomicAdd(&g_degi[ei[EE + e]], 1);
}

// block-level exclusive scan of degi (1024/block)
__global__ void __launch_bounds__(1024) k_scan1() {
    __shared__ int sm[1024];
    const int tid = threadIdx.x;
    const int i = blockIdx.x * 1024 + tid;
    const int v = (i < NN) ? g_degi[i] : 0;
    sm[tid] = v;
    __syncthreads();
    for (int o = 1; o < 1024; o <<= 1) {
        int t = (tid >= o) ? sm[tid - o] : 0;
        __syncthreads();
        sm[tid] += t;
        __syncthreads();
    }
    if (i < NN) g_part[i] = sm[tid] - v;          // exclusive
    if (tid == 1023) g_bsum[blockIdx.x] = sm[1023];
}

// scan of block sums + finalize offsets/dinv + per-graph node counts
__global__ void __launch_bounds__(1024) k_scan3(const int* __restrict__ batch) {
    __shared__ int sb[128];
    __shared__ int sv[128];
    const int tid = threadIdx.x;
    if (tid < 128) {
        int v = (tid < NB1) ? g_bsum[tid] : 0;
        sb[tid] = v; sv[tid] = v;
    }
    __syncthreads();
    for (int o = 1; o < 128; o <<= 1) {
        int t = 0;
        if (tid >= o && tid < 128) t = sb[tid - o];
        __syncthreads();
        if (tid < 128) sb[tid] += t;
        __syncthreads();
    }
    const int i = blockIdx.x * 1024 + tid;
    const unsigned act = __ballot_sync(0xffffffffu, i < NN);
    if (i >= NN) return;
    const int base = sb[blockIdx.x] - sv[blockIdx.x];   // exclusive block base
    const int o = g_part[i] + base;
    g_off[i] = o;
    g_cur[i] = o;
    g_dinv[i] = rsqrtf((float)g_degi[i] + 1.0f);
    // per-graph node counts (warp-aggregated)
    const int g = __ldg(&batch[i]);
    const unsigned m = __match_any_sync(act, g);
    if ((tid & 31) == (__ffs(m) - 1))
        atomicAdd(&g_cnt[g], (float)__popc(m));
}

// fill CSR + packed edge data {dinv[src], batch[src]}
__global__ void k_fill(const int* __restrict__ ei, const int* __restrict__ batch) {
    int e = blockIdx.x * blockDim.x + threadIdx.x;
    if (e >= EE) return;
    const int src = __ldg(&ei[e]);
    const int dst = __ldg(&ei[EE + e]);
    const float ds = __ldg(&g_dinv[src]);
    const int gs = __ldg(&batch[src]);
    const int pos = atomicAdd(&g_cur[dst], 1);
    g_csr[pos] = src;
    g_edat[pos] = make_uint2(__float_as_uint(ds), (unsigned)gs);
}

// xd[n] = x[n] * dinv[n], fp16 rows (64B)
__global__ void k_xd(const float* __restrict__ x) {
    const int gid = blockIdx.x * blockDim.x + threadIdx.x;
    const int n = gid >> 3;
    const int t = gid & 7;
    if (n >= NN) return;
    const float d = __ldg(&g_dinv[n]);
    const float4 v = *(const float4*)(x + (long)n * INC + t * 4);
    union { uint2 uu; __half2 h[2]; } pk;
    pk.h[0] = __floats2half2_rn(v.x * d, v.y * d);
    pk.h[1] = __floats2half2_rn(v.z * d, v.w * d);
    *(uint2*)((__half*)g_xd + (long)n * INC + t * 4) = pk.uu;
}

// ------------------------------------------------------------------
// conv0 gather on fp16 xd rows (quarter-warp/node, HADD2 tree groups):
// out[n] = dinv[n] * ( sum_s xd[s] + xd[n] )     fp32 inter-group merge
// ------------------------------------------------------------------
__global__ void __launch_bounds__(256)
k_gather32xh(float* __restrict__ out) {
    const int wid = threadIdx.x >> 5;
    const int lane = threadIdx.x & 31;
    const int q = lane >> 3;
    const int l8 = lane & 7;
    const int n = blockIdx.x * 32 + wid * 4 + q;
    if (n >= NN) return;
    const int o = __ldg(&g_off[n]);
    const int d = __ldg(&g_degi[n]);
    const float dn = __ldg(&g_dinv[n]);
    const __half* xd = (const __half*)g_xd;

    float a0, a1, a2, a3;
    {
        const uint2 u = *(const uint2*)(xd + (long)n * INC + l8 * 4);
        const float2 f0 = __half22float2(*(const __half2*)&u.x);
        const float2 f1 = __half22float2(*(const __half2*)&u.y);
        a0 = f0.x; a1 = f0.y; a2 = f1.x; a3 = f1.y;
    }
    int i = 0;
    for (; i + 8 <= d; i += 8) {
        int s[8]; uint2 u[8];
#pragma unroll
        for (int m = 0; m < 8; m++) s[m] = __ldg(&g_csr[o + i + m]);
#pragma unroll
        for (int m = 0; m < 8; m++) u[m] = *(const uint2*)(xd + (long)s[m] * INC + l8 * 4);
        // tree HADD2 per channel pair
#pragma unroll
        for (int t = 0; t < 2; t++) {
            const __half2 h0 = ((const __half2*)&u[0])[t];
            const __half2 h1 = ((const __half2*)&u[1])[t];
            const __half2 h2 = ((const __half2*)&u[2])[t];
            const __half2 h3 = ((const __half2*)&u[3])[t];
            const __half2 h4 = ((const __half2*)&u[4])[t];
            const __half2 h5 = ((const __half2*)&u[5])[t];
            const __half2 h6 = ((const __half2*)&u[6])[t];
            const __half2 h7 = ((const __half2*)&u[7])[t];
            const __half2 sgrp = __hadd2(__hadd2(__hadd2(h0, h1), __hadd2(h2, h3)),
                                         __hadd2(__hadd2(h4, h5), __hadd2(h6, h7)));
            const float2 f = __half22float2(sgrp);
            if (t == 0) { a0 += f.x; a1 += f.y; }
            else        { a2 += f.x; a3 += f.y; }
        }
    }
    for (; i + 4 <= d; i += 4) {
        int s[4]; uint2 u[4];
#pragma unroll
        for (int m = 0; m < 4; m++) s[m] = __ldg(&g_csr[o + i + m]);
#pragma unroll
        for (int m = 0; m < 4; m++) u[m] = *(const uint2*)(xd + (long)s[m] * INC + l8 * 4);
#pragma unroll
        for (int t = 0; t < 2; t++) {
            const __half2 sgrp = __hadd2(__hadd2(((const __half2*)&u[0])[t], ((const __half2*)&u[1])[t]),
                                         __hadd2(((const __half2*)&u[2])[t], ((const __half2*)&u[3])[t]));
            const float2 f = __half22float2(sgrp);
            if (t == 0) { a0 += f.x; a1 += f.y; }
            else        { a2 += f.x; a3 += f.y; }
        }
    }
    for (; i < d; i++) {
        const int s = __ldg(&g_csr[o + i]);
        const uint2 u = *(const uint2*)(xd + (long)s * INC + l8 * 4);
        const float2 f0 = __half22float2(*(const __half2*)&u.x);
        const float2 f1 = __half22float2(*(const __half2*)&u.y);
        a0 += f0.x; a1 += f0.y; a2 += f1.x; a3 += f1.y;
    }
    float4 r;
    r.x = a0 * dn; r.y = a1 * dn; r.z = a2 * dn; r.w = a3 * dn;
    *(float4*)(out + (long)n * INC + l8 * 4) = r;
}

// ------------------------------------------------------------------
// shared gather core, fp16 64-ch payload, HADD2 tree groups (encoder only)
// ------------------------------------------------------------------
__device__ __forceinline__ void gather64h_core(const __half* __restrict__ Ph,
                                               int n, int l8, float acc[8]) {
    const int o = __ldg(&g_off[n]);
    const int d = __ldg(&g_degi[n]);
    {
        uint4 u = *(const uint4*)(Ph + (long)n * HC + l8 * 8);
        const __half2* h = (const __half2*)&u;
#pragma unroll
        for (int m = 0; m < 4; m++) {
            float2 f = __half22float2(h[m]);
            acc[2 * m] = f.x; acc[2 * m + 1] = f.y;
        }
    }
    int i = 0;
    for (; i + 8 <= d; i += 8) {
        int s[8]; uint4 u[8];
#pragma unroll
        for (int m = 0; m < 8; m++) s[m] = __ldg(&g_csr[o + i + m]);
#pragma unroll
        for (int m = 0; m < 8; m++) u[m] = *(const uint4*)(Ph + (long)s[m] * HC + l8 * 8);
#pragma unroll
        for (int t = 0; t < 4; t++) {
            const __half2 h0 = ((const __half2*)&u[0])[t];
            const __half2 h1 = ((const __half2*)&u[1])[t];
            const __half2 h2 = ((const __half2*)&u[2])[t];
            const __half2 h3 = ((const __half2*)&u[3])[t];
            const __half2 h4 = ((const __half2*)&u[4])[t];
            const __half2 h5 = ((const __half2*)&u[5])[t];
            const __half2 h6 = ((const __half2*)&u[6])[t];
            const __half2 h7 = ((const __half2*)&u[7])[t];
            const __half2 sgrp = __hadd2(__hadd2(__hadd2(h0, h1), __hadd2(h2, h3)),
                                         __hadd2(__hadd2(h4, h5), __hadd2(h6, h7)));
            const float2 f = __half22float2(sgrp);
            acc[2 * t] += f.x; acc[2 * t + 1] += f.y;
        }
    }
    for (; i + 4 <= d; i += 4) {
        int s[4]; uint4 u[4];
#pragma unroll
        for (int m = 0; m < 4; m++) s[m] = __ldg(&g_csr[o + i + m]);
#pragma unroll
        for (int m = 0; m < 4; m++) u[m] = *(const uint4*)(Ph + (long)s[m] * HC + l8 * 8);
#pragma unroll
        for (int t = 0; t < 4; t++) {
            const __half2 sgrp = __hadd2(__hadd2(((const __half2*)&u[0])[t], ((const __half2*)&u[1])[t]),
                                         __hadd2(((const __half2*)&u[2])[t], ((const __half2*)&u[3])[t]));
            const float2 f = __half22float2(sgrp);
            acc[2 * t] += f.x; acc[2 * t + 1] += f.y;
        }
    }
    for (; i < d; i++) {
        const int s = __ldg(&g_csr[o + i]);
        const uint4 u = *(const uint4*)(Ph + (long)s * HC + l8 * 8);
        const __half2* h = (const __half2*)&u;
#pragma unroll
        for (int t = 0; t < 4; t++) {
            float2 f = __half22float2(h[t]);
            acc[2 * t] += f.x; acc[2 * t + 1] += f.y;
        }
    }
}

// ------------------------------------------------------------------
// 64-ch fp16-payload gather -> fp32 rows (conv1): out = dinv*(sum)+b
// ------------------------------------------------------------------
__global__ void __launch_bounds__(256)
k_gather64h(const __half* __restrict__ Ph, const float* __restrict__ b,
            float* __restrict__ out) {
    const int wid = threadIdx.x >> 5;
    const int lane = threadIdx.x & 31;
    const int q = lane >> 3;
    const int l8 = lane & 7;
    const int n = blockIdx.x * 32 + wid * 4 + q;
    if (n >= NN) return;

    float acc[8];
    gather64h_core(Ph, n, l8, acc);

    const float dn = __ldg(&g_dinv[n]);
    const float4 bA = *(const float4*)(b + l8 * 8);
    const float4 bB = *(const float4*)(b + l8 * 8 + 4);
    float4 rA, rB;
    rA.x = fmaf(acc[0], dn, bA.x); rA.y = fmaf(acc[1], dn, bA.y);
    rA.z = fmaf(acc[2], dn, bA.z); rA.w = fmaf(acc[3], dn, bA.w);
    rB.x = fmaf(acc[4], dn, bB.x); rB.y = fmaf(acc[5], dn, bB.y);
    rB.z = fmaf(acc[6], dn, bB.z); rB.w = fmaf(acc[7], dn, bB.w);
    float* op = out + (long)n * HC + l8 * 8;
    *(float4*)(op) = rA; *(float4*)(op + 4) = rB;
}

// ------------------------------------------------------------------
// conv2: gather(P2 fp16) + bias + relu + pool accumulation (no row write)
// ------------------------------------------------------------------
__global__ void __launch_bounds__(256)
k_conv2pool(const __half* __restrict__ P2, const float* __restrict__ b2,
            const int* __restrict__ batch) {
    const int tid = threadIdx.x;
    const int wid = tid >> 5, lane = tid & 31;
    const int q = lane >> 3, l8 = lane & 7;
    const int n = blockIdx.x * 32 + wid * 4 + q;   // grid exact: NN/32 blocks

    float acc[8];
    gather64h_core(P2, n, l8, acc);
    const float dn = __ldg(&g_dinv[n]);
    const float4 bA = __ldg((const float4*)(b2 + l8 * 8));
    const float4 bB = __ldg((const float4*)(b2 + l8 * 8 + 4));
    float v[8];
    v[0] = fmaxf(fmaf(acc[0], dn, bA.x), 0.f);
    v[1] = fmaxf(fmaf(acc[1], dn, bA.y), 0.f);
    v[2] = fmaxf(fmaf(acc[2], dn, bA.z), 0.f);
    v[3] = fmaxf(fmaf(acc[3], dn, bA.w), 0.f);
    v[4] = fmaxf(fmaf(acc[4], dn, bB.x), 0.f);
    v[5] = fmaxf(fmaf(acc[5], dn, bB.y), 0.f);
    v[6] = fmaxf(fmaf(acc[6], dn, bB.z), 0.f);
    v[7] = fmaxf(fmaf(acc[7], dn, bB.w), 0.f);

    const int g = __ldg(&batch[n]);
    const unsigned F = 0xffffffffu;
    const int gb = __shfl_sync(F, g, 0);
    const bool uni = __all_sync(F, g == gb);
    if (uni) {
#pragma unroll
        for (int t = 0; t < 8; t++) {
            v[t] += __shfl_xor_sync(F, v[t], 8);
            v[t] += __shfl_xor_sync(F, v[t], 16);
        }
        if (lane < 8) {
#pragma unroll
            for (int t = 0; t < 8; t++)
                atomicAdd(&g_sums[g * HC + l8 * 8 + t], v[t]);
        }
    } else {
#pragma unroll
        for (int t = 0; t < 8; t++)
            atomicAdd(&g_sums[g * HC + l8 * 8 + t], v[t]);
    }
}

// ------------------------------------------------------------------
// dec0 gather via graph table + packed edge data (half-warp/node, unroll 8)
// ------------------------------------------------------------------
__global__ void __launch_bounds__(256)
k_gather_tab(const int* __restrict__ batch, const float* __restrict__ b,
             float* __restrict__ out) {
    __shared__ float XWs[GG * HC];      // 16KB
    const int tid = threadIdx.x;
    {
        const float4* s4 = (const float4*)g_XW;
        float4* d4 = (float4*)XWs;
        for (int i = tid; i < GG * HC / 4; i += 256) d4[i] = s4[i];
    }
    __syncthreads();

    const int wid = tid >> 5;
    const int lane = tid & 31;
    const int h = lane >> 4;
    const int l16 = lane & 15;
    const int n = blockIdx.x * 16 + wid * 2 + h;
    if (n >= NN) return;
    const int o = __ldg(&g_off[n]);
    const int d = __ldg(&g_degi[n]);
    const float dn = __ldg(&g_dinv[n]);

    const int gn = __ldg(&batch[n]);
    float4 acc = *(const float4*)(XWs + gn * HC + l16 * 4);
    acc.x *= dn; acc.y *= dn; acc.z *= dn; acc.w *= dn;

    int i = 0;
    for (; i + 8 <= d; i += 8) {
        uint2 e[8];
#pragma unroll
        for (int m = 0; m < 8; m++) e[m] = __ldg(&g_edat[o + i + m]);
#pragma unroll
        for (int m = 0; m < 8; m++) {
            const float ds = __uint_as_float(e[m].x);
            const float4 v = *(const float4*)(XWs + e[m].y * HC + l16 * 4);
            acc.x = fmaf(v.x, ds, acc.x);
            acc.y = fmaf(v.y, ds, acc.y);
            acc.z = fmaf(v.z, ds, acc.z);
            acc.w = fmaf(v.w, ds, acc.w);
        }
    }
    for (; i + 4 <= d; i += 4) {
        uint2 e[4];
#pragma unroll
        for (int m = 0; m < 4; m++) e[m] = __ldg(&g_edat[o + i + m]);
#pragma unroll
        for (int m = 0; m < 4; m++) {
            const float ds = __uint_as_float(e[m].x);
            const float4 v = *(const float4*)(XWs + e[m].y * HC + l16 * 4);
            acc.x = fmaf(v.x, ds, acc.x);
            acc.y = fmaf(v.y, ds, acc.y);
            acc.z = fmaf(v.z, ds, acc.z);
            acc.w = fmaf(v.w, ds, acc.w);
        }
    }
    for (; i < d; i++) {
        const uint2 e = __ldg(&g_edat[o + i]);
        const float ds = __uint_as_float(e.x);
        const float4 v = *(const float4*)(XWs + e.y * HC + l16 * 4);
        acc.x = fmaf(v.x, ds, acc.x); acc.y = fmaf(v.y, ds, acc.y);
        acc.z = fmaf(v.z, ds, acc.z); acc.w = fmaf(v.w, ds, acc.w);
    }
    const float4 b4 = __ldg(&((const float4*)b)[l16]);
    float4 r;
    r.x = fmaf(acc.x, dn, b4.x); r.y = fmaf(acc.y, dn, b4.y);
    r.z = fmaf(acc.z, dn, b4.z); r.w = fmaf(acc.w, dn, b4.w);
    *(float4*)(out + (long)n * HC + l16 * 4) = r;
}

// 32-ch fp32 payload gather (quarter-warp/node, unroll 8) — decoder output path
__global__ void __launch_bounds__(256)
k_gather32p(const float* __restrict__ P, const float* __restrict__ b,
            float* __restrict__ out) {
    const int wid = threadIdx.x >> 5;
    const int lane = threadIdx.x & 31;
    const int q = lane >> 3;
    const int l8 = lane & 7;
    const int n = blockIdx.x * 32 + wid * 4 + q;
    if (n >= NN) return;
    const int o = __ldg(&g_off[n]);
    const int d = __ldg(&g_degi[n]);

    float4 acc = *(const float4*)(P + (long)n * INC + l8 * 4);  // self
    int i = 0;
    for (; i + 8 <= d; i += 8) {
        int s[8]; float4 v[8];
#pragma unroll
        for (int m = 0; m < 8; m++) s[m] = __ldg(&g_csr[o + i + m]);
#pragma unroll
        for (int m = 0; m < 8; m++) v[m] = *(const float4*)(P + (long)s[m] * INC + l8 * 4);
#pragma unroll
        for (int m = 0; m < 8; m++) {
            acc.x += v[m].x; acc.y += v[m].y; acc.z += v[m].z; acc.w += v[m].w;
        }
    }
    for (; i + 4 <= d; i += 4) {
        int s[4]; float4 v[4];
#pragma unroll
        for (int m = 0; m < 4; m++) s[m] = __ldg(&g_csr[o + i + m]);
#pragma unroll
        for (int m = 0; m < 4; m++) v[m] = *(const float4*)(P + (long)s[m] * INC + l8 * 4);
#pragma unroll
        for (int m = 0; m < 4; m++) {
            acc.x += v[m].x; acc.y += v[m].y; acc.z += v[m].z; acc.w += v[m].w;
        }
    }
    for (; i < d; i++) {
        const int s = __ldg(&g_csr[o + i]);
        const float4 v = *(const float4*)(P + (long)s * INC + l8 * 4);
        acc.x += v.x; acc.y += v.y; acc.z += v.z; acc.w += v.w;
    }
    const float dn = __ldg(&g_dinv[n]);
    const float4 b4 = __ldg(&((const float4*)b)[l8]);
    float4 r;
    r.x = fmaf(acc.x, dn, b4.x); r.y = fmaf(acc.y, dn, b4.y);
    r.z = fmaf(acc.z, dn, b4.z); r.w = fmaf(acc.w, dn, b4.w);
    *(float4*)(out + (long)n * INC + l8 * 4) = r;
}

// ------------------------------------------------------------------
// GEMM: register-blocked 4 nodes x 8 channels per thread. blockDim=256.
// MODE 0: out = in@W + b ; MODE 1: fp32 payload ; MODE 2: fp16 payload
// ------------------------------------------------------------------
template <int KIN, int COUT, bool RELUIN, int MODE>
__global__ void __launch_bounds__(256, 3)
k_gemm(const float* __restrict__ in,
       const float* __restrict__ W,
       const float* __restrict__ b,
       float* __restrict__ dst) {
    constexpr int TPN = COUT / 8;
    constexpr int NG  = 256 / TPN;
    constexpr int NPB = NG * 4;
    constexpr int XSS = KIN + 1;

    __shared__ float Ws[KIN * COUT];
    __shared__ float bs[COUT];
    __shared__ float xs[NPB * XSS];

    const int tid = threadIdx.x;
    const int n0 = blockIdx.x * NPB;

    {
        const float4* W4 = (const float4*)W;
        float4* Ws4 = (float4*)Ws;
#pragma unroll
        for (int i = tid; i < KIN * COUT / 4; i += 256) Ws4[i] = W4[i];
    }
    if (tid < COUT) bs[tid] = (MODE == 0) ? b[tid] : 0.f;

    {
        constexpr int QPR = KIN / 4;
        constexpr int NQ = NPB * QPR;
        for (int i = tid; i < NQ; i += 256) {
            const int row = i / QPR;
            const int qc = i % QPR;
            float4 v = make_float4(0.f, 0.f, 0.f, 0.f);
            if (n0 + row < NN) {
                v = *(const float4*)(in + (long)(n0 + row) * KIN + qc * 4);
                if (RELUIN) {
                    v.x = fmaxf(v.x, 0.f); v.y = fmaxf(v.y, 0.f);
                    v.z = fmaxf(v.z, 0.f); v.w = fmaxf(v.w, 0.f);
                }
            }
            float* p = xs + row * XSS + qc * 4;
            p[0] = v.x; p[1] = v.y; p[2] = v.z; p[3] = v.w;
        }
    }
    __syncthreads();

    const int tc = tid % TPN;
    const int ng = tid / TPN;
    const int c0 = tc * 8;
    const int nb = ng * 4;

    float acc[4][8];
#pragma unroll
    for (int j = 0; j < 4; j++)
#pragma unroll
        for (int m = 0; m < 8; m++) acc[j][m] = 0.f;

    const float4* Ws4 = (const float4*)Ws;
#pragma unroll 8
    for (int k = 0; k < KIN; k++) {
        const float4 w0 = Ws4[(k * COUT + c0) >> 2];
        const float4 w1 = Ws4[((k * COUT + c0) >> 2) + 1];
        float xv[4];
#pragma unroll
        for (int j = 0; j < 4; j++) xv[j] = xs[(nb + j) * XSS + k];
#pragma unroll
        for (int j = 0; j < 4; j++) {
            acc[j][0] = fmaf(xv[j], w0.x, acc[j][0]);
            acc[j][1] = fmaf(xv[j], w0.y, acc[j][1]);
            acc[j][2] = fmaf(xv[j], w0.z, acc[j][2]);
            acc[j][3] = fmaf(xv[j], w0.w, acc[j][3]);
            acc[j][4] = fmaf(xv[j], w1.x, acc[j][4]);
            acc[j][5] = fmaf(xv[j], w1.y, acc[j][5]);
            acc[j][6] = fmaf(xv[j], w1.z, acc[j][6]);
            acc[j][7] = fmaf(xv[j], w1.w, acc[j][7]);
        }
    }

#pragma unroll
    for (int j = 0; j < 4; j++) {
        const int n = n0 + nb + j;
        if (n >= NN) break;
        if (MODE == 2) {
            const float d = g_dinv[n];
            union { uint4 u; __half2 h[4]; } pk;
            pk.h[0] = __floats2half2_rn(acc[j][0] * d, acc[j][1] * d);
            pk.h[1] = __floats2half2_rn(acc[j][2] * d, acc[j][3] * d);
            pk.h[2] = __floats2half2_rn(acc[j][4] * d, acc[j][5] * d);
            pk.h[3] = __floats2half2_rn(acc[j][6] * d, acc[j][7] * d);
            *(uint4*)((__half*)dst + (long)n * COUT + c0) = pk.u;
        } else if (MODE == 1) {
            const float d = g_dinv[n];
            float4 o0, o1;
            o0.x = acc[j][0] * d; o0.y = acc[j][1] * d;
            o0.z = acc[j][2] * d; o0.w = acc[j][3] * d;
            o1.x = acc[j][4] * d; o1.y = acc[j][5] * d;
            o1.z = acc[j][6] * d; o1.w = acc[j][7] * d;
            float* op = dst + (long)n * COUT + c0;
            *(float4*)(op) = o0; *(float4*)(op + 4) = o1;
        } else {
            float4 o0, o1;
            o0.x = acc[j][0] + bs[c0 + 0]; o0.y = acc[j][1] + bs[c0 + 1];
            o0.z = acc[j][2] + bs[c0 + 2]; o0.w = acc[j][3] + bs[c0 + 3];
            o1.x = acc[j][4] + bs[c0 + 4]; o1.y = acc[j][5] + bs[c0 + 5];
            o1.z = acc[j][6] + bs[c0 + 6]; o1.w = acc[j][7] + bs[c0 + 7];
            float* op = dst + (long)n * COUT + c0;
            *(float4*)(op) = o0; *(float4*)(op + 4) = o1;
        }
    }
}

// ------------------------------------------------------------------
// Fused latent path: z = (sums/cnt)@Wp + bp  (also to d_out);
// D = relu(z@Wdp + bdp); XW = D @ W_dec0.   One block of 1024.
// ------------------------------------------------------------------
__global__ void __launch_bounds__(1024)
k_latent(const float* __restrict__ Wp, const float* __restrict__ bp,
         const float* __restrict__ Wdp, const float* __restrict__ bdp,
         const float* __restrict__ Wd0, float* __restrict__ zout) {
    __shared__ float zs[GG * LC];
    __shared__ float Ds[GG * HC];
    __shared__ float Wd0s[HC * HC];
    const int tid = threadIdx.x;        // 0..1023 = GG*LC exactly

    {
        const int g = tid / LC, l = tid % LC;
        const float inv = 1.0f / fmaxf(g_cnt[g], 1.0f);
        float s = bp[l];
#pragma unroll
        for (int k = 0; k < HC; k++)
            s = fmaf(g_sums[g * HC + k] * inv, Wp[k * LC + l], s);
        zs[g * LC + l] = s;
        zout[g * LC + l] = s;
    }
    for (int i = tid; i < HC * HC; i += 1024) Wd0s[i] = Wd0[i];
    __syncthreads();

    for (int i = tid; i < GG * HC; i += 1024) {
        const int g = i / HC, c = i % HC;
        float s = bdp[c];
#pragma unroll
        for (int k = 0; k < LC; k++) s = fmaf(zs[g * LC + k], Wdp[k * HC + c], s);
        Ds[i] = fmaxf(s, 0.f);
    }
    __syncthreads();

    for (int i = tid; i < GG * HC; i += 1024) {
        const int g = i / HC, c = i % HC;
        float s = 0.f;
#pragma unroll 16
        for (int k = 0; k < HC; k++) s = fmaf(Ds[g * HC + k], Wd0s[k * HC + c], s);
        g_XW[i] = s;
    }
}

// ------------------------------------------------------------------
extern "C" void kernel_launch(void* const* d_in, const int* in_sizes, int n_in,
                              void* d_out, int out_size) {
    const float* x       = (const float*)d_in[0];
    const int*   ei      = (const int*)  d_in[1];
    const int*   batch   = (const int*)  d_in[2];
    const float* W_enc0  = (const float*)d_in[3];
    const float* b_enc0  = (const float*)d_in[4];
    const float* W_enc1  = (const float*)d_in[5];
    const float* b_enc1  = (const float*)d_in[6];
    const float* W_enc2  = (const float*)d_in[7];
    const float* b_enc2  = (const float*)d_in[8];
    const float* W_proj  = (const float*)d_in[9];
    const float* b_proj  = (const float*)d_in[10];
    const float* W_decp  = (const float*)d_in[11];
    const float* b_decp  = (const float*)d_in[12];
    const float* W_dec0  = (const float*)d_in[13];
    const float* b_dec0  = (const float*)d_in[14];
    const float* W_dec1  = (const float*)d_in[15];
    const float* b_dec1  = (const float*)d_in[16];

    float* out  = (float*)d_out;
    float* xrec = out;             // [NN, INC]
    float* zout = out + NN * INC;  // [GG, LC]

    float *p_xws, *p_buf0, *p_buf1;
    cudaGetSymbolAddress((void**)&p_xws,  g_xws);
    cudaGetSymbolAddress((void**)&p_buf0, g_buf0);
    cudaGetSymbolAddress((void**)&p_buf1, g_buf1);

    const int TB = 256;
    const int gN    = (NN + TB - 1) / TB;
    const int gE    = (EE + TB - 1) / TB;
    const int gA64  = (NN + 127) / 128;     // GEMM COUT=64
    const int gA32  = (NN + 255) / 256;     // GEMM COUT=32
    const int gG64  = (NN + 15) / 16;       // gather_tab: 16 nodes/block
    const int gG32  = (NN + 31) / 32;       // quarter-warp gathers: 32 nodes/block
    const int gN8   = (NN * 8 + TB - 1) / TB;

    // ---- degree, CSR build, dinv, per-graph counts ----
    k_init<<<gN, TB>>>();
    k_count<<<gE, TB>>>(ei);
    k_scan1<<<NB1, 1024>>>();
    k_scan3<<<NB1, 1024>>>(batch);
    k_fill<<<gE, TB>>>(ei, batch);
    k_xd<<<gN8, TB>>>(x);

    // ---- conv0 (gather fp16 xd, then GEMM) ----
    k_gather32xh<<<gG32, TB>>>(p_buf1);
    k_gemm<INC, HC, false, 0><<<gA64, TB>>>(p_buf1, W_enc0, b_enc0, p_buf0);

    // ---- conv1 (fp16 payload) ----
    k_gemm<HC, HC, true, 2><<<gA64, TB>>>(p_buf0, W_enc1, nullptr, p_xws);
    k_gather64h<<<gG32, TB>>>((const __half*)p_xws, b_enc1, p_buf1);
    // ---- conv2 (fp16 payload), gather fused with pool ----
    k_gemm<HC, HC, true, 2><<<gA64, TB>>>(p_buf1, W_enc2, nullptr, p_buf0);
    k_conv2pool<<<gG32, TB>>>((const __half*)p_buf0, b_enc2, batch);

    // ---- latent + decoder head ----
    k_latent<<<1, 1024>>>(W_proj, b_proj, W_decp, b_decp, W_dec0, zout);

    // ---- dec conv0 via graph table + packed edge data ----
    k_gather_tab<<<gG64, TB>>>(batch, b_dec0, p_buf1);

    // ---- dec conv1 (fp32 payload for output accuracy) ----
    k_gemm<HC, INC, true, 1><<<gA32, TB>>>(p_buf1, W_dec1, nullptr, p_xws);
    k_gather32p<<<gG32, TB>>>(p_xws, b_dec1, xrec);
}

// round 16
// speedup vs baseline: 1.0545x; 1.0545x over previous
#include <cuda_runtime.h>
#include <cuda_fp16.h>
#include <math.h>

#define NN 100000
#define EE 1600000
#define INC 32
#define HC  64
#define LC  16
#define GG  64
#define NB1 98          // ceil(NN/1024) scan blocks

// ---- device scratch (static, no allocation) ----
__device__ int   g_degi[NN];
__device__ int   g_part[NN];
__device__ int   g_off[NN];
__device__ int   g_cur[NN];
__device__ int   g_csr[EE];
__device__ int   g_bsum[128];
__device__ float g_dinv[NN];
__device__ float g_xws[NN * HC];    // payload buffers (fp16/fp32 reinterpreted)
__device__ float g_buf0[NN * HC];
__device__ float g_buf1[NN * HC];
__device__ float g_sums[GG * HC];
__device__ float g_cnt[GG];
__device__ float g_XW[GG * HC];     // (relu(z@Wdp+b)) @ W_dec0, per graph

// ------------------------------------------------------------------
__global__ void k_init() {
    int i = blockIdx.x * blockDim.x + threadIdx.x;
    if (i < NN) g_degi[i] = 0;
    if (i < GG * HC) g_sums[i] = 0.f;
    if (i < GG) g_cnt[i] = 0.f;
}

__global__ void k_count(const int* __restrict__ ei) {
    int e = blockIdx.x * blockDim.x + threadIdx.x;
    if (e < EE) atomicAdd(&g_degi[ei[EE + e]], 1);
}

// block-level exclusive scan of degi (1024/block, warp-shuffle)
__global__ void __launch_bounds__(1024) k_scan1() {
    __shared__ int ws[32];
    const int tid = threadIdx.x;
    const int lane = tid & 31, w = tid >> 5;
    const int i = blockIdx.x * 1024 + tid;
    const int v = (i < NN) ? g_degi[i] : 0;
    int sc = v;
#pragma unroll
    for (int o = 1; o < 32; o <<= 1) {
        int t = __shfl_up_sync(0xffffffffu, sc, o);
        if (lane >= o) sc += t;
    }
    if (lane == 31) ws[w] = sc;
    __syncthreads();
    if (w == 0) {
        int s = ws[lane];
#pragma unroll
        for (int o = 1; o < 32; o <<= 1) {
            int t = __shfl_up_sync(0xffffffffu, s, o);
            if (lane >= o) s += t;
        }
        ws[lane] = s;
    }
    __syncthreads();
    const int base = (w > 0) ? ws[w - 1] : 0;
    if (i < NN) g_part[i] = base + sc - v;          // exclusive
    if (tid == 1023) g_bsum[blockIdx.x] = ws[31];
}

// scan of block sums + finalize offsets/dinv + per-graph node counts
__global__ void __launch_bounds__(1024) k_scan3(const int* __restrict__ batch) {
    __shared__ int sb[128];
    __shared__ int sv[128];
    const int tid = threadIdx.x;
    if (tid < 128) {
        int v = (tid < NB1) ? g_bsum[tid] : 0;
        sb[tid] = v; sv[tid] = v;
    }
    __syncthreads();
    for (int o = 1; o < 128; o <<= 1) {
        int t = 0;
        if (tid >= o && tid < 128) t = sb[tid - o];
        __syncthreads();
        if (tid < 128) sb[tid] += t;
        __syncthreads();
    }
    const int i = blockIdx.x * 1024 + tid;
    const unsigned act = __ballot_sync(0xffffffffu, i < NN);
    if (i >= NN) return;
    const int base = sb[blockIdx.x] - sv[blockIdx.x];   // exclusive block base
    const int o = g_part[i] + base;
    g_off[i] = o;
    g_cur[i] = o;
    g_dinv[i] = rsqrtf((float)g_degi[i] + 1.0f);
    const int g = __ldg(&batch[i]);
    const unsigned m = __match_any_sync(act, g);
    if ((tid & 31) == (__ffs(m) - 1))
        atomicAdd(&g_cnt[g], (float)__popc(m));
}

__global__ void k_fill(const int* __restrict__ ei) {
    int e = blockIdx.x * blockDim.x + threadIdx.x;
    if (e >= EE) return;
    const int src = __ldg(&ei[e]);
    const int dst = __ldg(&ei[EE + e]);
    const int pos = atomicAdd(&g_cur[dst], 1);
    g_csr[pos] = src;
}

// ------------------------------------------------------------------
// conv0 gather (quarter-warp/node, float4 row, unroll 8) -> fp16 agg rows
// agg[n] = dinv[n] * ( sum_s x[s]*dinv[s]  +  x[n]*dinv[n] )
// ------------------------------------------------------------------
__global__ void __launch_bounds__(256)
k_gather32x(const float* __restrict__ x, __half* __restrict__ out) {
    const int wid = threadIdx.x >> 5;
    const int lane = threadIdx.x & 31;
    const int q = lane >> 3;
    const int l8 = lane & 7;
    const int n = blockIdx.x * 32 + wid * 4 + q;
    if (n >= NN) return;
    const int o = __ldg(&g_off[n]);
    const int d = __ldg(&g_degi[n]);
    const float dn = __ldg(&g_dinv[n]);

    float4 acc = make_float4(0.f, 0.f, 0.f, 0.f);
    int i = 0;
    for (; i + 8 <= d; i += 8) {
        int s[8]; float ds[8]; float4 v[8];
#pragma unroll
        for (int m = 0; m < 8; m++) s[m] = __ldg(&g_csr[o + i + m]);
#pragma unroll
        for (int m = 0; m < 8; m++) ds[m] = __ldg(&g_dinv[s[m]]);
#pragma unroll
        for (int m = 0; m < 8; m++) v[m] = *(const float4*)(x + (long)s[m] * INC + l8 * 4);
#pragma unroll
        for (int m = 0; m < 8; m++) {
            acc.x = fmaf(v[m].x, ds[m], acc.x);
            acc.y = fmaf(v[m].y, ds[m], acc.y);
            acc.z = fmaf(v[m].z, ds[m], acc.z);
            acc.w = fmaf(v[m].w, ds[m], acc.w);
        }
    }
    for (; i + 4 <= d; i += 4) {
        int s[4]; float ds[4]; float4 v[4];
#pragma unroll
        for (int m = 0; m < 4; m++) s[m] = __ldg(&g_csr[o + i + m]);
#pragma unroll
        for (int m = 0; m < 4; m++) ds[m] = __ldg(&g_dinv[s[m]]);
#pragma unroll
        for (int m = 0; m < 4; m++) v[m] = *(const float4*)(x + (long)s[m] * INC + l8 * 4);
#pragma unroll
        for (int m = 0; m < 4; m++) {
            acc.x = fmaf(v[m].x, ds[m], acc.x);
            acc.y = fmaf(v[m].y, ds[m], acc.y);
            acc.z = fmaf(v[m].z, ds[m], acc.z);
            acc.w = fmaf(v[m].w, ds[m], acc.w);
        }
    }
    for (; i < d; i++) {
        const int s = __ldg(&g_csr[o + i]);
        const float ds = __ldg(&g_dinv[s]);
        const float4 v = *(const float4*)(x + (long)s * INC + l8 * 4);
        acc.x = fmaf(v.x, ds, acc.x); acc.y = fmaf(v.y, ds, acc.y);
        acc.z = fmaf(v.z, ds, acc.z); acc.w = fmaf(v.w, ds, acc.w);
    }
    const float4 xv = *(const float4*)(x + (long)n * INC + l8 * 4);
    union { uint2 u; __half2 h[2]; } pk;
    pk.h[0] = __floats2half2_rn(fmaf(xv.x, dn, acc.x) * dn,
                                fmaf(xv.y, dn, acc.y) * dn);
    pk.h[1] = __floats2half2_rn(fmaf(xv.z, dn, acc.z) * dn,
                                fmaf(xv.w, dn, acc.w) * dn);
    *(uint2*)(out + (long)n * INC + l8 * 4) = pk.u;
}

// ------------------------------------------------------------------
// shared gather core for fp16 64-ch payload (quarter-warp, unroll 8)
// fp32 accumulate
// ------------------------------------------------------------------
__device__ __forceinline__ void gather64h_core(const __half* __restrict__ Ph,
                                               int n, int l8, float acc[8]) {
    const int o = __ldg(&g_off[n]);
    const int d = __ldg(&g_degi[n]);
    {
        uint4 u = *(const uint4*)(Ph + (long)n * HC + l8 * 8);
        const __half2* h = (const __half2*)&u;
#pragma unroll
        for (int m = 0; m < 4; m++) {
            float2 f = __half22float2(h[m]);
            acc[2 * m] = f.x; acc[2 * m + 1] = f.y;
        }
    }
    int i = 0;
    for (; i + 8 <= d; i += 8) {
        int s[8]; uint4 u[8];
#pragma unroll
        for (int m = 0; m < 8; m++) s[m] = __ldg(&g_csr[o + i + m]);
#pragma unroll
        for (int m = 0; m < 8; m++) u[m] = *(const uint4*)(Ph + (long)s[m] * HC + l8 * 8);
#pragma unroll
        for (int m = 0; m < 8; m++) {
            const __half2* h = (const __half2*)&u[m];
#pragma unroll
            for (int t = 0; t < 4; t++) {
                float2 f = __half22float2(h[t]);
                acc[2 * t] += f.x; acc[2 * t + 1] += f.y;
            }
        }
    }
    for (; i + 4 <= d; i += 4) {
        int s[4]; uint4 u[4];
#pragma unroll
        for (int m = 0; m < 4; m++) s[m] = __ldg(&g_csr[o + i + m]);
#pragma unroll
        for (int m = 0; m < 4; m++) u[m] = *(const uint4*)(Ph + (long)s[m] * HC + l8 * 8);
#pragma unroll
        for (int m = 0; m < 4; m++) {
            const __half2* h = (const __half2*)&u[m];
#pragma unroll
            for (int t = 0; t < 4; t++) {
                float2 f = __half22float2(h[t]);
                acc[2 * t] += f.x; acc[2 * t + 1] += f.y;
            }
        }
    }
    for (; i < d; i++) {
        const int s = __ldg(&g_csr[o + i]);
        const uint4 u = *(const uint4*)(Ph + (long)s * HC + l8 * 8);
        const __half2* h = (const __half2*)&u;
#pragma unroll
        for (int t = 0; t < 4; t++) {
            float2 f = __half22float2(h[t]);
            acc[2 * t] += f.x; acc[2 * t + 1] += f.y;
        }
    }
}

// ------------------------------------------------------------------
// conv1 gather -> relu'd fp16 rows: out = relu(dinv*(sum)+b)  fp16
// ------------------------------------------------------------------
__global__ void __launch_bounds__(256)
k_gather64h(const __half* __restrict__ Ph, const float* __restrict__ b,
            __half* __restrict__ out) {
    const int wid = threadIdx.x >> 5;
    const int lane = threadIdx.x & 31;
    const int q = lane >> 3;
    const int l8 = lane & 7;
    const int n = blockIdx.x * 32 + wid * 4 + q;
    if (n >= NN) return;

    float acc[8];
    gather64h_core(Ph, n, l8, acc);

    const float dn = __ldg(&g_dinv[n]);
    const float4 bA = *(const float4*)(b + l8 * 8);
    const float4 bB = *(const float4*)(b + l8 * 8 + 4);
    union { uint4 u; __half2 h[4]; } pk;
    pk.h[0] = __floats2half2_rn(fmaxf(fmaf(acc[0], dn, bA.x), 0.f),
                                fmaxf(fmaf(acc[1], dn, bA.y), 0.f));
    pk.h[1] = __floats2half2_rn(fmaxf(fmaf(acc[2], dn, bA.z), 0.f),
                                fmaxf(fmaf(acc[3], dn, bA.w), 0.f));
    pk.h[2] = __floats2half2_rn(fmaxf(fmaf(acc[4], dn, bB.x), 0.f),
                                fmaxf(fmaf(acc[5], dn, bB.y), 0.f));
    pk.h[3] = __floats2half2_rn(fmaxf(fmaf(acc[6], dn, bB.z), 0.f),
                                fmaxf(fmaf(acc[7], dn, bB.w), 0.f));
    *(uint4*)(out + (long)n * HC + l8 * 8) = pk.u;
}

// ------------------------------------------------------------------
// conv2: gather(P2 fp16) + bias + relu + pool accumulation (no row write)
// ------------------------------------------------------------------
__global__ void __launch_bounds__(256)
k_conv2pool(const __half* __restrict__ P2, const float* __restrict__ b2,
            const int* __restrict__ batch) {
    const int tid = threadIdx.x;
    const int wid = tid >> 5, lane = tid & 31;
    const int q = lane >> 3, l8 = lane & 7;
    const int n = blockIdx.x * 32 + wid * 4 + q;   // grid exact: NN/32 blocks

    float acc[8];
    gather64h_core(P2, n, l8, acc);
    const float dn = __ldg(&g_dinv[n]);
    const float4 bA = __ldg((const float4*)(b2 + l8 * 8));
    const float4 bB = __ldg((const float4*)(b2 + l8 * 8 + 4));
    float v[8];
    v[0] = fmaxf(fmaf(acc[0], dn, bA.x), 0.f);
    v[1] = fmaxf(fmaf(acc[1], dn, bA.y), 0.f);
    v[2] = fmaxf(fmaf(acc[2], dn, bA.z), 0.f);
    v[3] = fmaxf(fmaf(acc[3], dn, bA.w), 0.f);
    v[4] = fmaxf(fmaf(acc[4], dn, bB.x), 0.f);
    v[5] = fmaxf(fmaf(acc[5], dn, bB.y), 0.f);
    v[6] = fmaxf(fmaf(acc[6], dn, bB.z), 0.f);
    v[7] = fmaxf(fmaf(acc[7], dn, bB.w), 0.f);

    const int g = __ldg(&batch[n]);
    const unsigned F = 0xffffffffu;
    const int gb = __shfl_sync(F, g, 0);
    const bool uni = __all_sync(F, g == gb);
    if (uni) {
#pragma unroll
        for (int t = 0; t < 8; t++) {
            v[t] += __shfl_xor_sync(F, v[t], 8);
            v[t] += __shfl_xor_sync(F, v[t], 16);
        }
        if (lane < 8) {
#pragma unroll
            for (int t = 0; t < 8; t++)
                atomicAdd(&g_sums[g * HC + l8 * 8 + t], v[t]);
        }
    } else {
#pragma unroll
        for (int t = 0; t < 8; t++)
            atomicAdd(&g_sums[g * HC + l8 * 8 + t], v[t]);
    }
}

// dec0 gather via graph table (half-warp/node, smem table, unroll 4) - fp32
__global__ void __launch_bounds__(256)
k_gather_tab(const int* __restrict__ batch, const float* __restrict__ b,
             float* __restrict__ out) {
    __shared__ float XWs[GG * HC];      // 16KB
    const int tid = threadIdx.x;
    {
        const float4* s4 = (const float4*)g_XW;
        float4* d4 = (float4*)XWs;
        for (int i = tid; i < GG * HC / 4; i += 256) d4[i] = s4[i];
    }
    __syncthreads();

    const int wid = tid >> 5;
    const int lane = tid & 31;
    const int h = lane >> 4;
    const int l16 = lane & 15;
    const int n = blockIdx.x * 16 + wid * 2 + h;
    if (n >= NN) return;
    const int o = __ldg(&g_off[n]);
    const int d = __ldg(&g_degi[n]);
    const float dn = __ldg(&g_dinv[n]);

    const int gn = __ldg(&batch[n]);
    float4 acc = *(const float4*)(XWs + gn * HC + l16 * 4);
    acc.x *= dn; acc.y *= dn; acc.z *= dn; acc.w *= dn;

    int i = 0;
    for (; i + 4 <= d; i += 4) {
        int s[4]; int g[4]; float ds[4];
#pragma unroll
        for (int m = 0; m < 4; m++) s[m] = __ldg(&g_csr[o + i + m]);
#pragma unroll
        for (int m = 0; m < 4; m++) g[m] = __ldg(&batch[s[m]]);
#pragma unroll
        for (int m = 0; m < 4; m++) ds[m] = __ldg(&g_dinv[s[m]]);
#pragma unroll
        for (int m = 0; m < 4; m++) {
            const float4 v = *(const float4*)(XWs + g[m] * HC + l16 * 4);
            acc.x = fmaf(v.x, ds[m], acc.x);
            acc.y = fmaf(v.y, ds[m], acc.y);
            acc.z = fmaf(v.z, ds[m], acc.z);
            acc.w = fmaf(v.w, ds[m], acc.w);
        }
    }
    for (; i < d; i++) {
        const int s = __ldg(&g_csr[o + i]);
        const int g = __ldg(&batch[s]);
        const float ds = __ldg(&g_dinv[s]);
        const float4 v = *(const float4*)(XWs + g * HC + l16 * 4);
        acc.x = fmaf(v.x, ds, acc.x); acc.y = fmaf(v.y, ds, acc.y);
        acc.z = fmaf(v.z, ds, acc.z); acc.w = fmaf(v.w, ds, acc.w);
    }
    const float4 b4 = __ldg(&((const float4*)b)[l16]);
    float4 r;
    r.x = fmaf(acc.x, dn, b4.x); r.y = fmaf(acc.y, dn, b4.y);
    r.z = fmaf(acc.z, dn, b4.z); r.w = fmaf(acc.w, dn, b4.w);
    *(float4*)(out + (long)n * HC + l16 * 4) = r;
}

// 32-ch fp32 payload gather (quarter-warp/node, unroll 8) — decoder output
__global__ void __launch_bounds__(256)
k_gather32p(const float* __restrict__ P, const float* __restrict__ b,
            float* __restrict__ out) {
    const int wid = threadIdx.x >> 5;
    const int lane = threadIdx.x & 31;
    const int q = lane >> 3;
    const int l8 = lane & 7;
    const int n = blockIdx.x * 32 + wid * 4 + q;
    if (n >= NN) return;
    const int o = __ldg(&g_off[n]);
    const int d = __ldg(&g_degi[n]);

    float4 acc = *(const float4*)(P + (long)n * INC + l8 * 4);  // self
    int i = 0;
    for (; i + 8 <= d; i += 8) {
        int s[8]; float4 v[8];
#pragma unroll
        for (int m = 0; m < 8; m++) s[m] = __ldg(&g_csr[o + i + m]);
#pragma unroll
        for (int m = 0; m < 8; m++) v[m] = *(const float4*)(P + (long)s[m] * INC + l8 * 4);
#pragma unroll
        for (int m = 0; m < 8; m++) {
            acc.x += v[m].x; acc.y += v[m].y; acc.z += v[m].z; acc.w += v[m].w;
        }
    }
    for (; i + 4 <= d; i += 4) {
        int s[4]; float4 v[4];
#pragma unroll
        for (int m = 0; m < 4; m++) s[m] = __ldg(&g_csr[o + i + m]);
#pragma unroll
        for (int m = 0; m < 4; m++) v[m] = *(const float4*)(P + (long)s[m] * INC + l8 * 4);
#pragma unroll
        for (int m = 0; m < 4; m++) {
            acc.x += v[m].x; acc.y += v[m].y; acc.z += v[m].z; acc.w += v[m].w;
        }
    }
    for (; i < d; i++) {
        const int s = __ldg(&g_csr[o + i]);
        const float4 v = *(const float4*)(P + (long)s * INC + l8 * 4);
        acc.x += v.x; acc.y += v.y; acc.z += v.z; acc.w += v.w;
    }
    const float dn = __ldg(&g_dinv[n]);
    const float4 b4 = __ldg(&((const float4*)b)[l8]);
    float4 r;
    r.x = fmaf(acc.x, dn, b4.x); r.y = fmaf(acc.y, dn, b4.y);
    r.z = fmaf(acc.z, dn, b4.z); r.w = fmaf(acc.w, dn, b4.w);
    *(float4*)(out + (long)n * INC + l8 * 4) = r;
}

// ------------------------------------------------------------------
// GEMM: register-blocked 4 nodes x 8 channels per thread. blockDim=256.
// MODE 0: out = in@W + b           fp32
// MODE 1: payload = (in@W)*dinv    fp32
// MODE 2: payload = (in@W)*dinv    fp16
// MODE 3: out = relu(in@W + b)     fp16
// HALFIN: input rows are fp16
// ------------------------------------------------------------------
template <int KIN, int COUT, bool RELUIN, int MODE, bool HALFIN>
__global__ void __launch_bounds__(256, 3)
k_gemm(const float* __restrict__ in,
       const float* __restrict__ W,
       const float* __restrict__ b,
       float* __restrict__ dst) {
    constexpr int TPN = COUT / 8;
    constexpr int NG  = 256 / TPN;
    constexpr int NPB = NG * 4;
    constexpr int XSS = KIN + 1;

    __shared__ float Ws[KIN * COUT];
    __shared__ float bs[COUT];
    __shared__ float xs[NPB * XSS];

    const int tid = threadIdx.x;
    const int n0 = blockIdx.x * NPB;

    {
        const float4* W4 = (const float4*)W;
        float4* Ws4 = (float4*)Ws;
#pragma unroll
        for (int i = tid; i < KIN * COUT / 4; i += 256) Ws4[i] = W4[i];
    }
    if (tid < COUT) bs[tid] = (MODE == 0 || MODE == 3) ? b[tid] : 0.f;

    {
        constexpr int QPR = KIN / 4;
        constexpr int NQ = NPB * QPR;
        for (int i = tid; i < NQ; i += 256) {
            const int row = i / QPR;
            const int qc = i % QPR;
            float4 v = make_float4(0.f, 0.f, 0.f, 0.f);
            if (n0 + row < NN) {
                if (HALFIN) {
                    const uint2 u = *(const uint2*)((const __half*)in +
                                    (long)(n0 + row) * KIN + qc * 4);
                    const float2 f0 = __half22float2(*(const __half2*)&u.x);
                    const float2 f1 = __half22float2(*(const __half2*)&u.y);
                    v = make_float4(f0.x, f0.y, f1.x, f1.y);
                } else {
                    v = *(const float4*)(in + (long)(n0 + row) * KIN + qc * 4);
                }
                if (RELUIN) {
                    v.x = fmaxf(v.x, 0.f); v.y = fmaxf(v.y, 0.f);
                    v.z = fmaxf(v.z, 0.f); v.w = fmaxf(v.w, 0.f);
                }
            }
            float* p = xs + row * XSS + qc * 4;
            p[0] = v.x; p[1] = v.y; p[2] = v.z; p[3] = v.w;
        }
    }
    __syncthreads();

    const int tc = tid % TPN;
    const int ng = tid / TPN;
    const int c0 = tc * 8;
    const int nb = ng * 4;

    float acc[4][8];
#pragma unroll
    for (int j = 0; j < 4; j++)
#pragma unroll
        for (int m = 0; m < 8; m++) acc[j][m] = 0.f;

    const float4* Ws4 = (const float4*)Ws;
#pragma unroll 8
    for (int k = 0; k < KIN; k++) {
        const float4 w0 = Ws4[(k * COUT + c0) >> 2];
        const float4 w1 = Ws4[((k * COUT + c0) >> 2) + 1];
        float xv[4];
#pragma unroll
        for (int j = 0; j < 4; j++) xv[j] = xs[(nb + j) * XSS + k];
#pragma unroll
        for (int j = 0; j < 4; j++) {
            acc[j][0] = fmaf(xv[j], w0.x, acc[j][0]);
            acc[j][1] = fmaf(xv[j], w0.y, acc[j][1]);
            acc[j][2] = fmaf(xv[j], w0.z, acc[j][2]);
            acc[j][3] = fmaf(xv[j], w0.w, acc[j][3]);
            acc[j][4] = fmaf(xv[j], w1.x, acc[j][4]);
            acc[j][5] = fmaf(xv[j], w1.y, acc[j][5]);
            acc[j][6] = fmaf(xv[j], w1.z, acc[j][6]);
            acc[j][7] = fmaf(xv[j], w1.w, acc[j][7]);
        }
    }

#pragma unroll
    for (int j = 0; j < 4; j++) {
        const int n = n0 + nb + j;
        if (n >= NN) break;
        if (MODE == 3) {
            union { uint4 u; __half2 h[4]; } pk;
            pk.h[0] = __floats2half2_rn(fmaxf(acc[j][0] + bs[c0 + 0], 0.f),
                                        fmaxf(acc[j][1] + bs[c0 + 1], 0.f));
            pk.h[1] = __floats2half2_rn(fmaxf(acc[j][2] + bs[c0 + 2], 0.f),
                                        fmaxf(acc[j][3] + bs[c0 + 3], 0.f));
            pk.h[2] = __floats2half2_rn(fmaxf(acc[j][4] + bs[c0 + 4], 0.f),
                                        fmaxf(acc[j][5] + bs[c0 + 5], 0.f));
            pk.h[3] = __floats2half2_rn(fmaxf(acc[j][6] + bs[c0 + 6], 0.f),
                                        fmaxf(acc[j][7] + bs[c0 + 7], 0.f));
            *(uint4*)((__half*)dst + (long)n * COUT + c0) = pk.u;
        } else if (MODE == 2) {
            const float d = g_dinv[n];
            union { uint4 u; __half2 h[4]; } pk;
            pk.h[0] = __floats2half2_rn(acc[j][0] * d, acc[j][1] * d);
            pk.h[1] = __floats2half2_rn(acc[j][2] * d, acc[j][3] * d);
            pk.h[2] = __floats2half2_rn(acc[j][4] * d, acc[j][5] * d);
            pk.h[3] = __floats2half2_rn(acc[j][6] * d, acc[j][7] * d);
            *(uint4*)((__half*)dst + (long)n * COUT + c0) = pk.u;
        } else if (MODE == 1) {
            const float d = g_dinv[n];
            float4 o0, o1;
            o0.x = acc[j][0] * d; o0.y = acc[j][1] * d;
            o0.z = acc[j][2] * d; o0.w = acc[j][3] * d;
            o1.x = acc[j][4] * d; o1.y = acc[j][5] * d;
            o1.z = acc[j][6] * d; o1.w = acc[j][7] * d;
            float* op = dst + (long)n * COUT + c0;
            *(float4*)(op) = o0; *(float4*)(op + 4) = o1;
        } else {
            float4 o0, o1;
            o0.x = acc[j][0] + bs[c0 + 0]; o0.y = acc[j][1] + bs[c0 + 1];
            o0.z = acc[j][2] + bs[c0 + 2]; o0.w = acc[j][3] + bs[c0 + 3];
            o1.x = acc[j][4] + bs[c0 + 4]; o1.y = acc[j][5] + bs[c0 + 5];
            o1.z = acc[j][6] + bs[c0 + 6]; o1.w = acc[j][7] + bs[c0 + 7];
            float* op = dst + (long)n * COUT + c0;
            *(float4*)(op) = o0; *(float4*)(op + 4) = o1;
        }
    }
}

// ------------------------------------------------------------------
// Fused latent path: z = (sums/cnt)@Wp + bp  (also to d_out);
// D = relu(z@Wdp + bdp); XW = D @ W_dec0.   One block of 1024.
// ------------------------------------------------------------------
__global__ void __launch_bounds__(1024)
k_latent(const float* __restrict__ Wp, const float* __restrict__ bp,
         const float* __restrict__ Wdp, const float* __restrict__ bdp,
         const float* __restrict__ Wd0, float* __restrict__ zout) {
    __shared__ float zs[GG * LC];
    __shared__ float Ds[GG * HC];
    __shared__ float Wd0s[HC * HC];
    const int tid = threadIdx.x;        // 0..1023 = GG*LC exactly

    {
        const int g = tid / LC, l = tid % LC;
        const float inv = 1.0f / fmaxf(g_cnt[g], 1.0f);
        float s = bp[l];
#pragma unroll
        for (int k = 0; k < HC; k++)
            s = fmaf(g_sums[g * HC + k] * inv, Wp[k * LC + l], s);
        zs[g * LC + l] = s;
        zout[g * LC + l] = s;
    }
    for (int i = tid; i < HC * HC; i += 1024) Wd0s[i] = Wd0[i];
    __syncthreads();

    for (int i = tid; i < GG * HC; i += 1024) {
        const int g = i / HC, c = i % HC;
        float s = bdp[c];
#pragma unroll
        for (int k = 0; k < LC; k++) s = fmaf(zs[g * LC + k], Wdp[k * HC + c], s);
        Ds[i] = fmaxf(s, 0.f);
    }
    __syncthreads();

    for (int i = tid; i < GG * HC; i += 1024) {
        const int g = i / HC, c = i % HC;
        float s = 0.f;
#pragma unroll 16
        for (int k = 0; k < HC; k++) s = fmaf(Ds[g * HC + k], Wd0s[k * HC + c], s);
        g_XW[i] = s;
    }
}

// ------------------------------------------------------------------
extern "C" void kernel_launch(void* const* d_in, const int* in_sizes, int n_in,
                              void* d_out, int out_size) {
    const float* x       = (const float*)d_in[0];
    const int*   ei      = (const int*)  d_in[1];
    const int*   batch   = (const int*)  d_in[2];
    const float* W_enc0  = (const float*)d_in[3];
    const float* b_enc0  = (const float*)d_in[4];
    const float* W_enc1  = (const float*)d_in[5];
    const float* b_enc1  = (const float*)d_in[6];
    const float* W_enc2  = (const float*)d_in[7];
    const float* b_enc2  = (const float*)d_in[8];
    const float* W_proj  = (const float*)d_in[9];
    const float* b_proj  = (const float*)d_in[10];
    const float* W_decp  = (const float*)d_in[11];
    const float* b_decp  = (const float*)d_in[12];
    const float* W_dec0  = (const float*)d_in[13];
    const float* b_dec0  = (const float*)d_in[14];
    const float* W_dec1  = (const float*)d_in[15];
    const float* b_dec1  = (const float*)d_in[16];

    float* out  = (float*)d_out;
    float* xrec = out;             // [NN, INC]
    float* zout = out + NN * INC;  // [GG, LC]

    float *p_xws, *p_buf0, *p_buf1;
    cudaGetSymbolAddress((void**)&p_xws,  g_xws);
    cudaGetSymbolAddress((void**)&p_buf0, g_buf0);
    cudaGetSymbolAddress((void**)&p_buf1, g_buf1);

    const int TB = 256;
    const int gN    = (NN + TB - 1) / TB;
    const int gE    = (EE + TB - 1) / TB;
    const int gA64  = (NN + 127) / 128;     // GEMM COUT=64
    const int gA32  = (NN + 255) / 256;     // GEMM COUT=32
    const int gG64  = (NN + 15) / 16;       // gather_tab: 16 nodes/block
    const int gG32  = (NN + 31) / 32;       // quarter-warp gathers: 32 nodes/block

    // ---- degree, CSR build, dinv, per-graph counts ----
    k_init<<<gN, TB>>>();
    k_count<<<gE, TB>>>(ei);
    k_scan1<<<NB1, 1024>>>();
    k_scan3<<<NB1, 1024>>>(batch);
    k_fill<<<gE, TB>>>(ei);

    // ---- conv0: gather (fp16 agg) -> GEMM0 (relu'd fp16 h0) ----
    k_gather32x<<<gG32, TB>>>(x, (__half*)p_buf1);
    k_gemm<INC, HC, false, 3, true><<<gA64, TB>>>(p_buf1, W_enc0, b_enc0, p_buf0);

    // ---- conv1: GEMM (fp16 P1) -> gather (relu'd fp16 h1) ----
    k_gemm<HC, HC, false, 2, true><<<gA64, TB>>>(p_buf0, W_enc1, nullptr, p_xws);
    k_gather64h<<<gG32, TB>>>((const __half*)p_xws, b_enc1, (__half*)p_buf1);
    // ---- conv2: GEMM (fp16 P2) -> gather fused with pool ----
    k_gemm<HC, HC, false, 2, true><<<gA64, TB>>>(p_buf1, W_enc2, nullptr, p_buf0);
    k_conv2pool<<<gG32, TB>>>((const __half*)p_buf0, b_enc2, batch);

    // ---- latent + decoder head ----
    k_latent<<<1, 1024>>>(W_proj, b_proj, W_decp, b_decp, W_dec0, zout);

    // ---- dec conv0 via graph table (fp32) ----
    k_gather_tab<<<gG64, TB>>>(batch, b_dec0, p_buf1);

    // ---- dec conv1 (fp32 payload for output accuracy) ----
    k_gemm<HC, INC, true, 1, false><<<gA32, TB>>>(p_buf1, W_dec1, nullptr, p_xws);
    k_gather32p<<<gG32, TB>>>(p_xws, b_dec1, xrec);
}

// round 17
// speedup vs baseline: 1.0725x; 1.0171x over previous
#include <cuda_runtime.h>
#include <cuda_fp16.h>
#include <math.h>

#define NN 100000
#define EE 1600000
#define INC 32
#define HC  64
#define LC  16
#define GG  64
#define NB1 98          // ceil(NN/1024) scan blocks

// ---- device scratch (static, no allocation) ----
__device__ int   g_degi[NN];
__device__ int   g_part[NN];
__device__ int   g_off[NN];
__device__ int   g_cur[NN];
__device__ int   g_csr[EE];
__device__ int   g_bsum[128];
__device__ float g_dinv[NN];
__device__ float g_xws[NN * HC];    // payload buffers (fp16/fp32 reinterpreted)
__device__ float g_buf0[NN * HC];
__device__ float g_buf1[NN * HC];
__device__ float g_sums[GG * HC];
__device__ float g_cnt[GG];
__device__ float g_XW[GG * HC];     // (relu(z@Wdp+b)) @ W_dec0, per graph

// ------------------------------------------------------------------
__global__ void k_init() {
    int i = blockIdx.x * blockDim.x + threadIdx.x;
    if (i < NN) g_degi[i] = 0;
    if (i < GG * HC) g_sums[i] = 0.f;
    if (i < GG) g_cnt[i] = 0.f;
}

__global__ void k_count(const int* __restrict__ ei) {
    int e = blockIdx.x * blockDim.x + threadIdx.x;
    if (e < EE) atomicAdd(&g_degi[ei[EE + e]], 1);
}

// block-level exclusive scan of degi (1024/block, warp-shuffle)
__global__ void __launch_bounds__(1024) k_scan1() {
    __shared__ int ws[32];
    const int tid = threadIdx.x;
    const int lane = tid & 31, w = tid >> 5;
    const int i = blockIdx.x * 1024 + tid;
    const int v = (i < NN) ? g_degi[i] : 0;
    int sc = v;
#pragma unroll
    for (int o = 1; o < 32; o <<= 1) {
        int t = __shfl_up_sync(0xffffffffu, sc, o);
        if (lane >= o) sc += t;
    }
    if (lane == 31) ws[w] = sc;
    __syncthreads();
    if (w == 0) {
        int s = ws[lane];
#pragma unroll
        for (int o = 1; o < 32; o <<= 1) {
            int t = __shfl_up_sync(0xffffffffu, s, o);
            if (lane >= o) s += t;
        }
        ws[lane] = s;
    }
    __syncthreads();
    const int base = (w > 0) ? ws[w - 1] : 0;
    if (i < NN) g_part[i] = base + sc - v;          // exclusive
    if (tid == 1023) g_bsum[blockIdx.x] = ws[31];
}

// scan of block sums + finalize offsets/dinv + per-graph node counts
__global__ void __launch_bounds__(1024) k_scan3(const int* __restrict__ batch) {
    __shared__ int sb[128];
    __shared__ int sv[128];
    const int tid = threadIdx.x;
    if (tid < 128) {
        int v = (tid < NB1) ? g_bsum[tid] : 0;
        sb[tid] = v; sv[tid] = v;
    }
    __syncthreads();
    for (int o = 1; o < 128; o <<= 1) {
        int t = 0;
        if (tid >= o && tid < 128) t = sb[tid - o];
        __syncthreads();
        if (tid < 128) sb[tid] += t;
        __syncthreads();
    }
    const int i = blockIdx.x * 1024 + tid;
    const unsigned act = __ballot_sync(0xffffffffu, i < NN);
    if (i >= NN) return;
    const int base = sb[blockIdx.x] - sv[blockIdx.x];   // exclusive block base
    const int o = g_part[i] + base;
    g_off[i] = o;
    g_cur[i] = o;
    g_dinv[i] = rsqrtf((float)g_degi[i] + 1.0f);
    const int g = __ldg(&batch[i]);
    const unsigned m = __match_any_sync(act, g);
    if ((tid & 31) == (__ffs(m) - 1))
        atomicAdd(&g_cnt[g], (float)__popc(m));
}

__global__ void k_fill(const int* __restrict__ ei) {
    int e = blockIdx.x * blockDim.x + threadIdx.x;
    if (e >= EE) return;
    const int src = __ldg(&ei[e]);
    const int dst = __ldg(&ei[EE + e]);
    const int pos = atomicAdd(&g_cur[dst], 1);
    g_csr[pos] = src;
}

// ------------------------------------------------------------------
// conv0 gather (quarter-warp/node, float4 row, unroll 8) -> fp16 agg rows
// agg[n] = dinv[n] * ( sum_s x[s]*dinv[s]  +  x[n]*dinv[n] )
// ------------------------------------------------------------------
__global__ void __launch_bounds__(256)
k_gather32x(const float* __restrict__ x, __half* __restrict__ out) {
    const int wid = threadIdx.x >> 5;
    const int lane = threadIdx.x & 31;
    const int q = lane >> 3;
    const int l8 = lane & 7;
    const int n = blockIdx.x * 32 + wid * 4 + q;
    if (n >= NN) return;
    const int o = __ldg(&g_off[n]);
    const int d = __ldg(&g_degi[n]);
    const float dn = __ldg(&g_dinv[n]);

    float4 acc = make_float4(0.f, 0.f, 0.f, 0.f);
    int i = 0;
    for (; i + 8 <= d; i += 8) {
        int s[8]; float ds[8]; float4 v[8];
#pragma unroll
        for (int m = 0; m < 8; m++) s[m] = __ldg(&g_csr[o + i + m]);
#pragma unroll
        for (int m = 0; m < 8; m++) ds[m] = __ldg(&g_dinv[s[m]]);
#pragma unroll
        for (int m = 0; m < 8; m++) v[m] = *(const float4*)(x + (long)s[m] * INC + l8 * 4);
#pragma unroll
        for (int m = 0; m < 8; m++) {
            acc.x = fmaf(v[m].x, ds[m], acc.x);
            acc.y = fmaf(v[m].y, ds[m], acc.y);
            acc.z = fmaf(v[m].z, ds[m], acc.z);
            acc.w = fmaf(v[m].w, ds[m], acc.w);
        }
    }
    for (; i + 4 <= d; i += 4) {
        int s[4]; float ds[4]; float4 v[4];
#pragma unroll
        for (int m = 0; m < 4; m++) s[m] = __ldg(&g_csr[o + i + m]);
#pragma unroll
        for (int m = 0; m < 4; m++) ds[m] = __ldg(&g_dinv[s[m]]);
#pragma unroll
        for (int m = 0; m < 4; m++) v[m] = *(const float4*)(x + (long)s[m] * INC + l8 * 4);
#pragma unroll
        for (int m = 0; m < 4; m++) {
            acc.x = fmaf(v[m].x, ds[m], acc.x);
            acc.y = fmaf(v[m].y, ds[m], acc.y);
            acc.z = fmaf(v[m].z, ds[m], acc.z);
            acc.w = fmaf(v[m].w, ds[m], acc.w);
        }
    }
    for (; i < d; i++) {
        const int s = __ldg(&g_csr[o + i]);
        const float ds = __ldg(&g_dinv[s]);
        const float4 v = *(const float4*)(x + (long)s * INC + l8 * 4);
        acc.x = fmaf(v.x, ds, acc.x); acc.y = fmaf(v.y, ds, acc.y);
        acc.z = fmaf(v.z, ds, acc.z); acc.w = fmaf(v.w, ds, acc.w);
    }
    const float4 xv = *(const float4*)(x + (long)n * INC + l8 * 4);
    union { uint2 u; __half2 h[2]; } pk;
    pk.h[0] = __floats2half2_rn(fmaf(xv.x, dn, acc.x) * dn,
                                fmaf(xv.y, dn, acc.y) * dn);
    pk.h[1] = __floats2half2_rn(fmaf(xv.z, dn, acc.z) * dn,
                                fmaf(xv.w, dn, acc.w) * dn);
    *(uint2*)(out + (long)n * INC + l8 * 4) = pk.u;
}

// ------------------------------------------------------------------
// shared gather core for fp16 64-ch payload (quarter-warp, unroll 8)
// fp32 accumulate
// ------------------------------------------------------------------
__device__ __forceinline__ void gather64h_core(const __half* __restrict__ Ph,
                                               int n, int l8, float acc[8]) {
    const int o = __ldg(&g_off[n]);
    const int d = __ldg(&g_degi[n]);
    {
        uint4 u = *(const uint4*)(Ph + (long)n * HC + l8 * 8);
        const __half2* h = (const __half2*)&u;
#pragma unroll
        for (int m = 0; m < 4; m++) {
            float2 f = __half22float2(h[m]);
            acc[2 * m] = f.x; acc[2 * m + 1] = f.y;
        }
    }
    int i = 0;
    for (; i + 8 <= d; i += 8) {
        int s[8]; uint4 u[8];
#pragma unroll
        for (int m = 0; m < 8; m++) s[m] = __ldg(&g_csr[o + i + m]);
#pragma unroll
        for (int m = 0; m < 8; m++) u[m] = *(const uint4*)(Ph + (long)s[m] * HC + l8 * 8);
#pragma unroll
        for (int m = 0; m < 8; m++) {
            const __half2* h = (const __half2*)&u[m];
#pragma unroll
            for (int t = 0; t < 4; t++) {
                float2 f = __half22float2(h[t]);
                acc[2 * t] += f.x; acc[2 * t + 1] += f.y;
            }
        }
    }
    for (; i + 4 <= d; i += 4) {
        int s[4]; uint4 u[4];
#pragma unroll
        for (int m = 0; m < 4; m++) s[m] = __ldg(&g_csr[o + i + m]);
#pragma unroll
        for (int m = 0; m < 4; m++) u[m] = *(const uint4*)(Ph + (long)s[m] * HC + l8 * 8);
#pragma unroll
        for (int m = 0; m < 4; m++) {
            const __half2* h = (const __half2*)&u[m];
#pragma unroll
            for (int t = 0; t < 4; t++) {
                float2 f = __half22float2(h[t]);
                acc[2 * t] += f.x; acc[2 * t + 1] += f.y;
            }
        }
    }
    for (; i < d; i++) {
        const int s = __ldg(&g_csr[o + i]);
        const uint4 u = *(const uint4*)(Ph + (long)s * HC + l8 * 8);
        const __half2* h = (const __half2*)&u;
#pragma unroll
        for (int t = 0; t < 4; t++) {
            float2 f = __half22float2(h[t]);
            acc[2 * t] += f.x; acc[2 * t + 1] += f.y;
        }
    }
}

// ------------------------------------------------------------------
// conv1 gather -> relu'd fp16 rows: out = relu(dinv*(sum)+b)  fp16
// ------------------------------------------------------------------
__global__ void __launch_bounds__(256)
k_gather64h(const __half* __restrict__ Ph, const float* __restrict__ b,
            __half* __restrict__ out) {
    const int wid = threadIdx.x >> 5;
    const int lane = threadIdx.x & 31;
    const int q = lane >> 3;
    const int l8 = lane & 7;
    const int n = blockIdx.x * 32 + wid * 4 + q;
    if (n >= NN) return;

    float acc[8];
    gather64h_core(Ph, n, l8, acc);

    const float dn = __ldg(&g_dinv[n]);
    const float4 bA = *(const float4*)(b + l8 * 8);
    const float4 bB = *(const float4*)(b + l8 * 8 + 4);
    union { uint4 u; __half2 h[4]; } pk;
    pk.h[0] = __floats2half2_rn(fmaxf(fmaf(acc[0], dn, bA.x), 0.f),
                                fmaxf(fmaf(acc[1], dn, bA.y), 0.f));
    pk.h[1] = __floats2half2_rn(fmaxf(fmaf(acc[2], dn, bA.z), 0.f),
                                fmaxf(fmaf(acc[3], dn, bA.w), 0.f));
    pk.h[2] = __floats2half2_rn(fmaxf(fmaf(acc[4], dn, bB.x), 0.f),
                                fmaxf(fmaf(acc[5], dn, bB.y), 0.f));
    pk.h[3] = __floats2half2_rn(fmaxf(fmaf(acc[6], dn, bB.z), 0.f),
                                fmaxf(fmaf(acc[7], dn, bB.w), 0.f));
    *(uint4*)(out + (long)n * HC + l8 * 8) = pk.u;
}

// ------------------------------------------------------------------
// conv2: gather(P2 fp16) + bias + relu + pool accumulation (no row write)
// ------------------------------------------------------------------
__global__ void __launch_bounds__(256)
k_conv2pool(const __half* __restrict__ P2, const float* __restrict__ b2,
            const int* __restrict__ batch) {
    const int tid = threadIdx.x;
    const int wid = tid >> 5, lane = tid & 31;
    const int q = lane >> 3, l8 = lane & 7;
    const int n = blockIdx.x * 32 + wid * 4 + q;   // grid exact: NN/32 blocks

    float acc[8];
    gather64h_core(P2, n, l8, acc);
    const float dn = __ldg(&g_dinv[n]);
    const float4 bA = __ldg((const float4*)(b2 + l8 * 8));
    const float4 bB = __ldg((const float4*)(b2 + l8 * 8 + 4));
    float v[8];
    v[0] = fmaxf(fmaf(acc[0], dn, bA.x), 0.f);
    v[1] = fmaxf(fmaf(acc[1], dn, bA.y), 0.f);
    v[2] = fmaxf(fmaf(acc[2], dn, bA.z), 0.f);
    v[3] = fmaxf(fmaf(acc[3], dn, bA.w), 0.f);
    v[4] = fmaxf(fmaf(acc[4], dn, bB.x), 0.f);
    v[5] = fmaxf(fmaf(acc[5], dn, bB.y), 0.f);
    v[6] = fmaxf(fmaf(acc[6], dn, bB.z), 0.f);
    v[7] = fmaxf(fmaf(acc[7], dn, bB.w), 0.f);

    const int g = __ldg(&batch[n]);
    const unsigned F = 0xffffffffu;
    const int gb = __shfl_sync(F, g, 0);
    const bool uni = __all_sync(F, g == gb);
    if (uni) {
#pragma unroll
        for (int t = 0; t < 8; t++) {
            v[t] += __shfl_xor_sync(F, v[t], 8);
            v[t] += __shfl_xor_sync(F, v[t], 16);
        }
        if (lane < 8) {
#pragma unroll
            for (int t = 0; t < 8; t++)
                atomicAdd(&g_sums[g * HC + l8 * 8 + t], v[t]);
        }
    } else {
#pragma unroll
        for (int t = 0; t < 8; t++)
            atomicAdd(&g_sums[g * HC + l8 * 8 + t], v[t]);
    }
}

// dec0 gather via graph table (half-warp/node, smem table) -> relu'd fp16
__global__ void __launch_bounds__(256)
k_gather_tab(const int* __restrict__ batch, const float* __restrict__ b,
             __half* __restrict__ out) {
    __shared__ float XWs[GG * HC];      // 16KB
    const int tid = threadIdx.x;
    {
        const float4* s4 = (const float4*)g_XW;
        float4* d4 = (float4*)XWs;
        for (int i = tid; i < GG * HC / 4; i += 256) d4[i] = s4[i];
    }
    __syncthreads();

    const int wid = tid >> 5;
    const int lane = tid & 31;
    const int h = lane >> 4;
    const int l16 = lane & 15;
    const int n = blockIdx.x * 16 + wid * 2 + h;
    if (n >= NN) return;
    const int o = __ldg(&g_off[n]);
    const int d = __ldg(&g_degi[n]);
    const float dn = __ldg(&g_dinv[n]);

    const int gn = __ldg(&batch[n]);
    float4 acc = *(const float4*)(XWs + gn * HC + l16 * 4);
    acc.x *= dn; acc.y *= dn; acc.z *= dn; acc.w *= dn;

    int i = 0;
    for (; i + 4 <= d; i += 4) {
        int s[4]; int g[4]; float ds[4];
#pragma unroll
        for (int m = 0; m < 4; m++) s[m] = __ldg(&g_csr[o + i + m]);
#pragma unroll
        for (int m = 0; m < 4; m++) g[m] = __ldg(&batch[s[m]]);
#pragma unroll
        for (int m = 0; m < 4; m++) ds[m] = __ldg(&g_dinv[s[m]]);
#pragma unroll
        for (int m = 0; m < 4; m++) {
            const float4 v = *(const float4*)(XWs + g[m] * HC + l16 * 4);
            acc.x = fmaf(v.x, ds[m], acc.x);
            acc.y = fmaf(v.y, ds[m], acc.y);
            acc.z = fmaf(v.z, ds[m], acc.z);
            acc.w = fmaf(v.w, ds[m], acc.w);
        }
    }
    for (; i < d; i++) {
        const int s = __ldg(&g_csr[o + i]);
        const int g = __ldg(&batch[s]);
        const float ds = __ldg(&g_dinv[s]);
        const float4 v = *(const float4*)(XWs + g * HC + l16 * 4);
        acc.x = fmaf(v.x, ds, acc.x); acc.y = fmaf(v.y, ds, acc.y);
        acc.z = fmaf(v.z, ds, acc.z); acc.w = fmaf(v.w, ds, acc.w);
    }
    const float4 b4 = __ldg(&((const float4*)b)[l16]);
    union { uint2 u; __half2 h2[2]; } pk;
    pk.h2[0] = __floats2half2_rn(fmaxf(fmaf(acc.x, dn, b4.x), 0.f),
                                 fmaxf(fmaf(acc.y, dn, b4.y), 0.f));
    pk.h2[1] = __floats2half2_rn(fmaxf(fmaf(acc.z, dn, b4.z), 0.f),
                                 fmaxf(fmaf(acc.w, dn, b4.w), 0.f));
    *(uint2*)(out + (long)n * HC + l16 * 4) = pk.u;
}

// 32-ch fp16 payload gather (quarter-warp/node, unroll 8) -> fp32 xrec
__global__ void __launch_bounds__(256)
k_gather32ph(const __half* __restrict__ Ph, const float* __restrict__ b,
             float* __restrict__ out) {
    const int wid = threadIdx.x >> 5;
    const int lane = threadIdx.x & 31;
    const int q = lane >> 3;
    const int l8 = lane & 7;
    const int n = blockIdx.x * 32 + wid * 4 + q;
    if (n >= NN) return;
    const int o = __ldg(&g_off[n]);
    const int d = __ldg(&g_degi[n]);

    float a0, a1, a2, a3;
    {
        const uint2 u = *(const uint2*)(Ph + (long)n * INC + l8 * 4);
        const float2 f0 = __half22float2(*(const __half2*)&u.x);
        const float2 f1 = __half22float2(*(const __half2*)&u.y);
        a0 = f0.x; a1 = f0.y; a2 = f1.x; a3 = f1.y;
    }
    int i = 0;
    for (; i + 8 <= d; i += 8) {
        int s[8]; uint2 u[8];
#pragma unroll
        for (int m = 0; m < 8; m++) s[m] = __ldg(&g_csr[o + i + m]);
#pragma unroll
        for (int m = 0; m < 8; m++) u[m] = *(const uint2*)(Ph + (long)s[m] * INC + l8 * 4);
#pragma unroll
        for (int m = 0; m < 8; m++) {
            const float2 f0 = __half22float2(*(const __half2*)&u[m].x);
            const float2 f1 = __half22float2(*(const __half2*)&u[m].y);
            a0 += f0.x; a1 += f0.y; a2 += f1.x; a3 += f1.y;
        }
    }
    for (; i + 4 <= d; i += 4) {
        int s[4]; uint2 u[4];
#pragma unroll
        for (int m = 0; m < 4; m++) s[m] = __ldg(&g_csr[o + i + m]);
#pragma unroll
        for (int m = 0; m < 4; m++) u[m] = *(const uint2*)(Ph + (long)s[m] * INC + l8 * 4);
#pragma unroll
        for (int m = 0; m < 4; m++) {
            const float2 f0 = __half22float2(*(const __half2*)&u[m].x);
            const float2 f1 = __half22float2(*(const __half2*)&u[m].y);
            a0 += f0.x; a1 += f0.y; a2 += f1.x; a3 += f1.y;
        }
    }
    for (; i < d; i++) {
        const int s = __ldg(&g_csr[o + i]);
        const uint2 u = *(const uint2*)(Ph + (long)s * INC + l8 * 4);
        const float2 f0 = __half22float2(*(const __half2*)&u.x);
        const float2 f1 = __half22float2(*(const __half2*)&u.y);
        a0 += f0.x; a1 += f0.y; a2 += f1.x; a3 += f1.y;
    }
    const float dn = __ldg(&g_dinv[n]);
    const float4 b4 = __ldg(&((const float4*)b)[l8]);
    float4 r;
    r.x = fmaf(a0, dn, b4.x); r.y = fmaf(a1, dn, b4.y);
    r.z = fmaf(a2, dn, b4.z); r.w = fmaf(a3, dn, b4.w);
    *(float4*)(out + (long)n * INC + l8 * 4) = r;
}

// ------------------------------------------------------------------
// GEMM: register-blocked 4 nodes x 8 channels per thread. blockDim=256.
// MODE 0: out = in@W + b           fp32
// MODE 1: payload = (in@W)*dinv    fp32
// MODE 2: payload = (in@W)*dinv    fp16
// MODE 3: out = relu(in@W + b)     fp16
// HALFIN: input rows are fp16
// ------------------------------------------------------------------
template <int KIN, int COUT, bool RELUIN, int MODE, bool HALFIN>
__global__ void __launch_bounds__(256, 3)
k_gemm(const float* __restrict__ in,
       const float* __restrict__ W,
       const float* __restrict__ b,
       float* __restrict__ dst) {
    constexpr int TPN = COUT / 8;
    constexpr int NG  = 256 / TPN;
    constexpr int NPB = NG * 4;
    constexpr int XSS = KIN + 1;

    __shared__ float Ws[KIN * COUT];
    __shared__ float bs[COUT];
    __shared__ float xs[NPB * XSS];

    const int tid = threadIdx.x;
    const int n0 = blockIdx.x * NPB;

    {
        const float4* W4 = (const float4*)W;
        float4* Ws4 = (float4*)Ws;
#pragma unroll
        for (int i = tid; i < KIN * COUT / 4; i += 256) Ws4[i] = W4[i];
    }
    if (tid < COUT) bs[tid] = (MODE == 0 || MODE == 3) ? b[tid] : 0.f;

    {
        constexpr int QPR = KIN / 4;
        constexpr int NQ = NPB * QPR;
        for (int i = tid; i < NQ; i += 256) {
            const int row = i / QPR;
            const int qc = i % QPR;
            float4 v = make_float4(0.f, 0.f, 0.f, 0.f);
            if (n0 + row < NN) {
                if (HALFIN) {
                    const uint2 u = *(const uint2*)((const __half*)in +
                                    (long)(n0 + row) * KIN + qc * 4);
                    const float2 f0 = __half22float2(*(const __half2*)&u.x);
                    const float2 f1 = __half22float2(*(const __half2*)&u.y);
                    v = make_float4(f0.x, f0.y, f1.x, f1.y);
                } else {
                    v = *(const float4*)(in + (long)(n0 + row) * KIN + qc * 4);
                }
                if (RELUIN) {
                    v.x = fmaxf(v.x, 0.f); v.y = fmaxf(v.y, 0.f);
                    v.z = fmaxf(v.z, 0.f); v.w = fmaxf(v.w, 0.f);
                }
            }
            float* p = xs + row * XSS + qc * 4;
            p[0] = v.x; p[1] = v.y; p[2] = v.z; p[3] = v.w;
        }
    }
    __syncthreads();

    const int tc = tid % TPN;
    const int ng = tid / TPN;
    const int c0 = tc * 8;
    const int nb = ng * 4;

    float acc[4][8];
#pragma unroll
    for (int j = 0; j < 4; j++)
#pragma unroll
        for (int m = 0; m < 8; m++) acc[j][m] = 0.f;

    const float4* Ws4 = (const float4*)Ws;
#pragma unroll 8
    for (int k = 0; k < KIN; k++) {
        const float4 w0 = Ws4[(k * COUT + c0) >> 2];
        const float4 w1 = Ws4[((k * COUT + c0) >> 2) + 1];
        float xv[4];
#pragma unroll
        for (int j = 0; j < 4; j++) xv[j] = xs[(nb + j) * XSS + k];
#pragma unroll
        for (int j = 0; j < 4; j++) {
            acc[j][0] = fmaf(xv[j], w0.x, acc[j][0]);
            acc[j][1] = fmaf(xv[j], w0.y, acc[j][1]);
            acc[j][2] = fmaf(xv[j], w0.z, acc[j][2]);
            acc[j][3] = fmaf(xv[j], w0.w, acc[j][3]);
            acc[j][4] = fmaf(xv[j], w1.x, acc[j][4]);
            acc[j][5] = fmaf(xv[j], w1.y, acc[j][5]);
            acc[j][6] = fmaf(xv[j], w1.z, acc[j][6]);
            acc[j][7] = fmaf(xv[j], w1.w, acc[j][7]);
        }
    }

#pragma unroll
    for (int j = 0; j < 4; j++) {
        const int n = n0 + nb + j;
        if (n >= NN) break;
        if (MODE == 3) {
            union { uint4 u; __half2 h[4]; } pk;
            pk.h[0] = __floats2half2_rn(fmaxf(acc[j][0] + bs[c0 + 0], 0.f),
                                        fmaxf(acc[j][1] + bs[c0 + 1], 0.f));
            pk.h[1] = __floats2half2_rn(fmaxf(acc[j][2] + bs[c0 + 2], 0.f),
                                        fmaxf(acc[j][3] + bs[c0 + 3], 0.f));
            pk.h[2] = __floats2half2_rn(fmaxf(acc[j][4] + bs[c0 + 4], 0.f),
                                        fmaxf(acc[j][5] + bs[c0 + 5], 0.f));
            pk.h[3] = __floats2half2_rn(fmaxf(acc[j][6] + bs[c0 + 6], 0.f),
                                        fmaxf(acc[j][7] + bs[c0 + 7], 0.f));
            *(uint4*)((__half*)dst + (long)n * COUT + c0) = pk.u;
        } else if (MODE == 2) {
            const float d = g_dinv[n];
            if (COUT == 32) {
                union { uint2 u; __half2 h[2]; } pk;
                pk.h[0] = __floats2half2_rn(acc[j][0] * d, acc[j][1] * d);
                pk.h[1] = __floats2half2_rn(acc[j][2] * d, acc[j][3] * d);
                *(uint2*)((__half*)dst + (long)n * COUT + c0) = pk.u;
                union { uint2 u; __half2 h[2]; } pk2;
                pk2.h[0] = __floats2half2_rn(acc[j][4] * d, acc[j][5] * d);
                pk2.h[1] = __floats2half2_rn(acc[j][6] * d, acc[j][7] * d);
                *(uint2*)((__half*)dst + (long)n * COUT + c0 + 4) = pk2.u;
            } else {
                union { uint4 u; __half2 h[4]; } pk;
                pk.h[0] = __floats2half2_rn(acc[j][0] * d, acc[j][1] * d);
                pk.h[1] = __floats2half2_rn(acc[j][2] * d, acc[j][3] * d);
                pk.h[2] = __floats2half2_rn(acc[j][4] * d, acc[j][5] * d);
                pk.h[3] = __floats2half2_rn(acc[j][6] * d, acc[j][7] * d);
                *(uint4*)((__half*)dst + (long)n * COUT + c0) = pk.u;
            }
        } else if (MODE == 1) {
            const float d = g_dinv[n];
            float4 o0, o1;
            o0.x = acc[j][0] * d; o0.y = acc[j][1] * d;
            o0.z = acc[j][2] * d; o0.w = acc[j][3] * d;
            o1.x = acc[j][4] * d; o1.y = acc[j][5] * d;
            o1.z = acc[j][6] * d; o1.w = acc[j][7] * d;
            float* op = dst + (long)n * COUT + c0;
            *(float4*)(op) = o0; *(float4*)(op + 4) = o1;
        } else {
            float4 o0, o1;
            o0.x = acc[j][0] + bs[c0 + 0]; o0.y = acc[j][1] + bs[c0 + 1];
            o0.z = acc[j][2] + bs[c0 + 2]; o0.w = acc[j][3] + bs[c0 + 3];
            o1.x = acc[j][4] + bs[c0 + 4]; o1.y = acc[j][5] + bs[c0 + 5];
            o1.z = acc[j][6] + bs[c0 + 6]; o1.w = acc[j][7] + bs[c0 + 7];
            float* op = dst + (long)n * COUT + c0;
            *(float4*)(op) = o0; *(float4*)(op + 4) = o1;
        }
    }
}

// ------------------------------------------------------------------
// Fused latent path: z = (sums/cnt)@Wp + bp  (also to d_out);
// D = relu(z@Wdp + bdp); XW = D @ W_dec0.   One block of 1024.
// ------------------------------------------------------------------
__global__ void __launch_bounds__(1024)
k_latent(const float* __restrict__ Wp, const float* __restrict__ bp,
         const float* __restrict__ Wdp, const float* __restrict__ bdp,
         const float* __restrict__ Wd0, float* __restrict__ zout) {
    __shared__ float zs[GG * LC];
    __shared__ float Ds[GG * HC];
    __shared__ float Wd0s[HC * HC];
    const int tid = threadIdx.x;        // 0..1023 = GG*LC exactly

    {
        const int g = tid / LC, l = tid % LC;
        const float inv = 1.0f / fmaxf(g_cnt[g], 1.0f);
        float s = bp[l];
#pragma unroll
        for (int k = 0; k < HC; k++)
            s = fmaf(g_sums[g * HC + k] * inv, Wp[k * LC + l], s);
        zs[g * LC + l] = s;
        zout[g * LC + l] = s;
    }
    for (int i = tid; i < HC * HC; i += 1024) Wd0s[i] = Wd0[i];
    __syncthreads();

    for (int i = tid; i < GG * HC; i += 1024) {
        const int g = i / HC, c = i % HC;
        float s = bdp[c];
#pragma unroll
        for (int k = 0; k < LC; k++) s = fmaf(zs[g * LC + k], Wdp[k * HC + c], s);
        Ds[i] = fmaxf(s, 0.f);
    }
    __syncthreads();

    for (int i = tid; i < GG * HC; i += 1024) {
        const int g = i / HC, c = i % HC;
        float s = 0.f;
#pragma unroll 16
        for (int k = 0; k < HC; k++) s = fmaf(Ds[g * HC + k], Wd0s[k * HC + c], s);
        g_XW[i] = s;
    }
}

// ------------------------------------------------------------------
extern "C" void kernel_launch(void* const* d_in, const int* in_sizes, int n_in,
                              void* d_out, int out_size) {
    const float* x       = (const float*)d_in[0];
    const int*   ei      = (const int*)  d_in[1];
    const int*   batch   = (const int*)  d_in[2];
    const float* W_enc0  = (const float*)d_in[3];
    const float* b_enc0  = (const float*)d_in[4];
    const float* W_enc1  = (const float*)d_in[5];
    const float* b_enc1  = (const float*)d_in[6];
    const float* W_enc2  = (const float*)d_in[7];
    const float* b_enc2  = (const float*)d_in[8];
    const float* W_proj  = (const float*)d_in[9];
    const float* b_proj  = (const float*)d_in[10];
    const float* W_decp  = (const float*)d_in[11];
    const float* b_decp  = (const float*)d_in[12];
    const float* W_dec0  = (const float*)d_in[13];
    const float* b_dec0  = (const float*)d_in[14];
    const float* W_dec1  = (const float*)d_in[15];
    const float* b_dec1  = (const float*)d_in[16];

    float* out  = (float*)d_out;
    float* xrec = out;             // [NN, INC]
    float* zout = out + NN * INC;  // [GG, LC]

    float *p_xws, *p_buf0, *p_buf1;
    cudaGetSymbolAddress((void**)&p_xws,  g_xws);
    cudaGetSymbolAddress((void**)&p_buf0, g_buf0);
    cudaGetSymbolAddress((void**)&p_buf1, g_buf1);

    const int TB = 256;
    const int gN    = (NN + TB - 1) / TB;
    const int gE    = (EE + TB - 1) / TB;
    const int gA64  = (NN + 127) / 128;     // GEMM COUT=64
    const int gA32  = (NN + 255) / 256;     // GEMM COUT=32
    const int gG64  = (NN + 15) / 16;       // gather_tab: 16 nodes/block
    const int gG32  = (NN + 31) / 32;       // quarter-warp gathers: 32 nodes/block

    // ---- degree, CSR build, dinv, per-graph counts ----
    k_init<<<gN, TB>>>();
    k_count<<<gE, TB>>>(ei);
    k_scan1<<<NB1, 1024>>>();
    k_scan3<<<NB1, 1024>>>(batch);
    k_fill<<<gE, TB>>>(ei);

    // ---- conv0: gather (fp16 agg) -> GEMM0 (relu'd fp16 h0) ----
    k_gather32x<<<gG32, TB>>>(x, (__half*)p_buf1);
    k_gemm<INC, HC, false, 3, true><<<gA64, TB>>>(p_buf1, W_enc0, b_enc0, p_buf0);

    // ---- conv1: GEMM (fp16 P1) -> gather (relu'd fp16 h1) ----
    k_gemm<HC, HC, false, 2, true><<<gA64, TB>>>(p_buf0, W_enc1, nullptr, p_xws);
    k_gather64h<<<gG32, TB>>>((const __half*)p_xws, b_enc1, (__half*)p_buf1);
    // ---- conv2: GEMM (fp16 P2) -> gather fused with pool ----
    k_gemm<HC, HC, false, 2, true><<<gA64, TB>>>(p_buf1, W_enc2, nullptr, p_buf0);
    k_conv2pool<<<gG32, TB>>>((const __half*)p_buf0, b_enc2, batch);

    // ---- latent + decoder head ----
    k_latent<<<1, 1024>>>(W_proj, b_proj, W_decp, b_decp, W_dec0, zout);

    // ---- dec conv0 via graph table -> relu'd fp16 rows ----
    k_gather_tab<<<gG64, TB>>>(batch, b_dec0, (__half*)p_buf1);

    // ---- dec conv1: GEMM (fp16 in, fp16 payload) -> final fp16 gather ----
    k_gemm<HC, INC, false, 2, true><<<gA32, TB>>>(p_buf1, W_dec1, nullptr, p_xws);
    k_gather32ph<<<gG32, TB>>>((const __half*)p_xws, b_dec1, xrec);
}